// round 2
// baseline (speedup 1.0000x reference)
#include <cuda_runtime.h>
#include <cstdint>

// Problem constants
#define BB 2
#define NN 10000
#define MM 320000
#define DD 256
#define HH 8
#define ROWS (BB * NN)          // 20000 flattened GEMM rows
#define TOTAL_E (BB * MM)       // 640000 (b, edge) pairs

// ---------------- scratch (device globals; no allocation allowed) ----------
__device__ float    g_q[(size_t)ROWS * DD];      // 20.48 MB
__device__ float    g_k[(size_t)ROWS * DD];      // 20.48 MB
__device__ float    g_seg[(size_t)BB * NN * HH]; // 640 KB
__device__ unsigned g_max;                       // ordered-uint global max
__device__ int      g_mask32[2 * MM];            // canonical int32 mask
__device__ int      g_is64;                      // detected mask dtype

// ordered-uint mapping: monotone float -> unsigned
__device__ __forceinline__ unsigned float_to_ord(float f) {
    unsigned u = __float_as_uint(f);
    return (u & 0x80000000u) ? ~u : (u | 0x80000000u);
}
__device__ __forceinline__ float ord_to_float(unsigned o) {
    return (o & 0x80000000u) ? __uint_as_float(o ^ 0x80000000u)
                             : __uint_as_float(~o);
}

// ---------------- K_pre0: detect mask dtype ---------------------------------
// If buffer holds int64 values in [0, 2^31): every odd 32-bit word is 0.
// If buffer holds int32 values: odd words are random indices, ~all nonzero.
__global__ void detect_mask_kernel(const unsigned* __restrict__ mraw) {
    __shared__ int any_nonzero;
    if (threadIdx.x == 0) any_nonzero = 0;
    __syncthreads();
    // sample 256 odd words (well within the smallest possible buffer: 2*MM int32)
    unsigned v = mraw[threadIdx.x * 2 + 1];
    if (v != 0u) atomicOr(&any_nonzero, 1);
    __syncthreads();
    if (threadIdx.x == 0) g_is64 = any_nonzero ? 0 : 1;
}

// ---------------- K_pre1: normalize mask to int32, clamped ------------------
__global__ void convert_mask_kernel(const void* __restrict__ mraw) {
    int t = blockIdx.x * blockDim.x + threadIdx.x;
    if (t >= 2 * MM) return;
    long long v;
    if (g_is64) v = ((const long long*)mraw)[t];
    else        v = (long long)((const int*)mraw)[t];
    int vi = (int)v;
    vi = vi < 0 ? 0 : (vi >= NN ? NN - 1 : vi);   // safety clamp
    g_mask32[t] = vi;
}

// ---------------- K0: reset scratch -----------------------------------------
__global__ void reset_kernel() {
    int t = blockIdx.x * blockDim.x + threadIdx.x;
    int nseg = BB * NN * HH;
    if (t < nseg) g_seg[t] = 0.0f;
    if (t == nseg) g_max = 0u;   // below every finite float's ord
}

// ---------------- K1: SGEMM  C[r,j] = sum_k A[r,k] * W[k,j] -----------------
// 128x128 block tile, 8x8 per thread, BK=8, 256 threads.
// blockIdx.z: 0 -> q = x_q @ w_q, 1 -> k = x_k @ w_k
__global__ void __launch_bounds__(256)
gemm_kernel(const float* __restrict__ xq, const float* __restrict__ xk,
            const float* __restrict__ wq, const float* __restrict__ wk) {
    const float* A = (blockIdx.z == 0) ? xq : xk;
    const float* W = (blockIdx.z == 0) ? wq : wk;
    float*       C = (blockIdx.z == 0) ? g_q : g_k;

    __shared__ float As[8][128];   // transposed A tile: [k][m]
    __shared__ float Bs[8][128];   // [k][n]

    const int tid = threadIdx.x;
    const int tx = tid % 16, ty = tid / 16;
    const int block_row = blockIdx.x * 128;
    const int block_col = blockIdx.y * 128;

    // load assignments
    const int a_row = tid >> 1;            // 0..127
    const int a_col = (tid & 1) * 4;       // 0 or 4
    const int b_row = tid >> 5;            // 0..7
    const int b_col = (tid & 31) * 4;      // 0..124

    float acc[8][8];
    #pragma unroll
    for (int i = 0; i < 8; i++)
        #pragma unroll
        for (int j = 0; j < 8; j++) acc[i][j] = 0.0f;

    for (int k0 = 0; k0 < DD; k0 += 8) {
        const int gr = block_row + a_row;
        float4 av = make_float4(0.f, 0.f, 0.f, 0.f);
        if (gr < ROWS)
            av = *(const float4*)(A + (size_t)gr * DD + k0 + a_col);
        As[a_col + 0][a_row] = av.x;
        As[a_col + 1][a_row] = av.y;
        As[a_col + 2][a_row] = av.z;
        As[a_col + 3][a_row] = av.w;

        *(float4*)&Bs[b_row][b_col] =
            *(const float4*)(W + (size_t)(k0 + b_row) * DD + block_col + b_col);
        __syncthreads();

        #pragma unroll
        for (int kk = 0; kk < 8; kk++) {
            float ra[8], rb[8];
            *(float4*)&ra[0] = *(const float4*)&As[kk][ty * 8 + 0];
            *(float4*)&ra[4] = *(const float4*)&As[kk][ty * 8 + 4];
            *(float4*)&rb[0] = *(const float4*)&Bs[kk][tx * 8 + 0];
            *(float4*)&rb[4] = *(const float4*)&Bs[kk][tx * 8 + 4];
            #pragma unroll
            for (int i = 0; i < 8; i++)
                #pragma unroll
                for (int j = 0; j < 8; j++)
                    acc[i][j] = fmaf(ra[i], rb[j], acc[i][j]);
        }
        __syncthreads();
    }

    #pragma unroll
    for (int i = 0; i < 8; i++) {
        const int gr = block_row + ty * 8 + i;
        if (gr < ROWS) {
            float* cp = C + (size_t)gr * DD + block_col + tx * 8;
            *(float4*)(cp + 0) = make_float4(acc[i][0], acc[i][1], acc[i][2], acc[i][3]);
            *(float4*)(cp + 4) = make_float4(acc[i][4], acc[i][5], acc[i][6], acc[i][7]);
        }
    }
}

// ---------------- K2: edge scores (one warp per (b, edge)) ------------------
// a[b,m,h] = dot(q[b,i0, 32h:32h+32], k[b,i1, 32h:32h+32]) / 16
// Writes a into d_out; tracks global max via ordered atomicMax.
__global__ void __launch_bounds__(256)
edge_scores_kernel(float* __restrict__ a_out) {
    __shared__ unsigned smax;
    if (threadIdx.x == 0) smax = 0u;
    __syncthreads();

    const int warp = (blockIdx.x * blockDim.x + threadIdx.x) >> 5;
    const int lane = threadIdx.x & 31;

    if (warp < TOTAL_E) {
        const int b = warp / MM;
        const int m = warp - b * MM;
        const int i0 = g_mask32[m];
        const int i1 = g_mask32[MM + m];

        const float4* q4 = (const float4*)(g_q + ((size_t)b * NN + i0) * DD);
        const float4* k4 = (const float4*)(g_k + ((size_t)b * NN + i1) * DD);

        float4 qa = q4[lane],      ka = k4[lane];
        float4 qb = q4[lane + 32], kb = k4[lane + 32];

        float p1 = qa.x * ka.x + qa.y * ka.y + qa.z * ka.z + qa.w * ka.w;
        float p2 = qb.x * kb.x + qb.y * kb.y + qb.z * kb.z + qb.w * kb.w;

        // reduce within 8-lane groups (head = contiguous 32-element block)
        #pragma unroll
        for (int off = 4; off > 0; off >>= 1) {
            p1 += __shfl_down_sync(0xffffffffu, p1, off, 8);
            p2 += __shfl_down_sync(0xffffffffu, p2, off, 8);
        }

        if ((lane & 7) == 0) {
            const int g = lane >> 3;          // 0..3
            const float v1 = p1 * 0.0625f;    // head g   (1/sqrt(256))
            const float v2 = p2 * 0.0625f;    // head g+4
            const size_t base = ((size_t)b * MM + m) * HH;
            a_out[base + g]     = v1;
            a_out[base + g + 4] = v2;
            atomicMax(&smax, float_to_ord(fmaxf(v1, v2)));
        }
    }
    __syncthreads();
    if (threadIdx.x == 0) atomicMax(&g_max, smax);
}

// ---------------- K3: e = exp(a - max) in place; seg scatter-add ------------
__global__ void __launch_bounds__(256)
exp_scatter_kernel(float* __restrict__ e) {
    const int t = blockIdx.x * blockDim.x + threadIdx.x;
    if (t >= TOTAL_E) return;
    const int b = t / MM;
    const int m = t - b * MM;
    const float amax = ord_to_float(g_max);
    const int i0 = g_mask32[m];

    const size_t base = (size_t)t * HH;
    float4 a0 = *(float4*)(e + base);
    float4 a1 = *(float4*)(e + base + 4);
    float v[8] = {a0.x, a0.y, a0.z, a0.w, a1.x, a1.y, a1.z, a1.w};

    float* segp = g_seg + ((size_t)b * NN + i0) * HH;
    #pragma unroll
    for (int h = 0; h < HH; h++) {
        float ev = __expf(v[h] - amax);
        v[h] = ev;
        atomicAdd(segp + h, ev);
    }
    *(float4*)(e + base)     = make_float4(v[0], v[1], v[2], v[3]);
    *(float4*)(e + base + 4) = make_float4(v[4], v[5], v[6], v[7]);
}

// ---------------- K4: out = e / (seg[idx] + 1e-16) in place ------------------
__global__ void __launch_bounds__(256)
normalize_kernel(float* __restrict__ e) {
    const int t = blockIdx.x * blockDim.x + threadIdx.x;
    if (t >= TOTAL_E) return;
    const int b = t / MM;
    const int m = t - b * MM;
    const int i0 = g_mask32[m];

    const float* segp = g_seg + ((size_t)b * NN + i0) * HH;
    const size_t base = (size_t)t * HH;
    float4 e0 = *(float4*)(e + base);
    float4 e1 = *(float4*)(e + base + 4);

    e0.x /= (segp[0] + 1e-16f);
    e0.y /= (segp[1] + 1e-16f);
    e0.z /= (segp[2] + 1e-16f);
    e0.w /= (segp[3] + 1e-16f);
    e1.x /= (segp[4] + 1e-16f);
    e1.y /= (segp[5] + 1e-16f);
    e1.z /= (segp[6] + 1e-16f);
    e1.w /= (segp[7] + 1e-16f);

    *(float4*)(e + base)     = e0;
    *(float4*)(e + base + 4) = e1;
}

// ---------------- launch ----------------------------------------------------
extern "C" void kernel_launch(void* const* d_in, const int* in_sizes, int n_in,
                              void* d_out, int out_size) {
    const float* x_q  = (const float*)d_in[0];
    const float* x_k  = (const float*)d_in[1];
    const void*  mask = (const void*)d_in[2];
    const float* w_q  = (const float*)d_in[3];
    const float* w_k  = (const float*)d_in[4];
    float* out = (float*)d_out;

    // K_pre: detect mask dtype (int32 vs int64) and normalize to int32
    detect_mask_kernel<<<1, 256>>>((const unsigned*)mask);
    convert_mask_kernel<<<(2 * MM + 255) / 256, 256>>>(mask);

    // K0: reset seg + max
    {
        int n = BB * NN * HH + 1;
        reset_kernel<<<(n + 255) / 256, 256>>>();
    }
    // K1: q = x_q@w_q, k = x_k@w_k
    {
        dim3 grid((ROWS + 127) / 128, DD / 128, 2);
        gemm_kernel<<<grid, 256>>>(x_q, x_k, w_q, w_k);
    }
    // K2: per-edge head scores -> d_out, global max
    {
        int warps_per_block = 256 / 32;
        int blocks = (TOTAL_E + warps_per_block - 1) / warps_per_block;
        edge_scores_kernel<<<blocks, 256>>>(out);
    }
    // K3: exp + segment scatter
    {
        int blocks = (TOTAL_E + 255) / 256;
        exp_scatter_kernel<<<blocks, 256>>>(out);
    }
    // K4: normalize
    {
        int blocks = (TOTAL_E + 255) / 256;
        normalize_kernel<<<blocks, 256>>>(out);
    }
}

// round 3
// speedup vs baseline: 1.3601x; 1.3601x over previous
#include <cuda_runtime.h>
#include <cuda_fp16.h>
#include <cstdint>

// Problem constants
#define BB 2
#define NN 10000
#define MM 320000
#define DD 256
#define HH 8
#define ROWS (BB * NN)          // 20000 flattened GEMM rows
#define TOTAL_E (BB * MM)       // 640000 (b, edge) pairs

// ---------------- scratch (device globals; no allocation allowed) ----------
__device__ __half g_qh[(size_t)ROWS * DD];      // 10.24 MB (fp16 q)
__device__ __half g_kh[(size_t)ROWS * DD];      // 10.24 MB (fp16 k)
__device__ float  g_seg[(size_t)BB * NN * HH];  // 640 KB
__device__ int    g_mask32[2 * MM];             // canonical int32 mask
__device__ int    g_is64;                       // detected mask dtype

// ---------------- K_pre0: detect mask dtype ---------------------------------
// int64 indices in [0,N): every odd 32-bit word is 0. int32: odd words random.
__global__ void detect_mask_kernel(const unsigned* __restrict__ mraw) {
    __shared__ int any_nonzero;
    if (threadIdx.x == 0) any_nonzero = 0;
    __syncthreads();
    unsigned v = mraw[threadIdx.x * 2 + 1];
    if (v != 0u) atomicOr(&any_nonzero, 1);
    __syncthreads();
    if (threadIdx.x == 0) g_is64 = any_nonzero ? 0 : 1;
}

// ---------------- K_pre1: normalize mask to int32 (clamped) + reset seg -----
__global__ void convert_mask_kernel(const void* __restrict__ mraw) {
    int t = blockIdx.x * blockDim.x + threadIdx.x;
    if (t < 2 * MM) {
        long long v;
        if (g_is64) v = ((const long long*)mraw)[t];
        else        v = (long long)((const int*)mraw)[t];
        int vi = (int)v;
        vi = vi < 0 ? 0 : (vi >= NN ? NN - 1 : vi);
        g_mask32[t] = vi;
    }
    if (t < BB * NN * HH) g_seg[t] = 0.0f;
}

// ---------------- K1: SGEMM  C[r,j] = sum_k A[r,k] * W[k,j], fp16 out -------
// 128x128 block tile, 8x8 per thread, BK=8, 256 threads, register prefetch.
// blockIdx.z: 0 -> q = x_q @ w_q, 1 -> k = x_k @ w_k
__global__ void __launch_bounds__(256)
gemm_kernel(const float* __restrict__ xq, const float* __restrict__ xk,
            const float* __restrict__ wq, const float* __restrict__ wk) {
    const float* A = (blockIdx.z == 0) ? xq : xk;
    const float* W = (blockIdx.z == 0) ? wq : wk;
    __half*      C = (blockIdx.z == 0) ? g_qh : g_kh;

    __shared__ float As[8][128];   // transposed A tile: [k][m]
    __shared__ float Bs[8][128];   // [k][n]

    const int tid = threadIdx.x;
    const int tx = tid % 16, ty = tid / 16;
    const int block_row = blockIdx.x * 128;
    const int block_col = blockIdx.y * 128;

    const int a_row = tid >> 1;            // 0..127
    const int a_col = (tid & 1) * 4;       // 0 or 4
    const int b_row = tid >> 5;            // 0..7
    const int b_col = (tid & 31) * 4;      // 0..124
    const int a_guard = (block_row + a_row) < ROWS;

    const float* a_ptr = A + (size_t)(block_row + a_row) * DD + a_col;
    const float* b_ptr = W + (size_t)b_row * DD + block_col + b_col;

    float acc[8][8];
    #pragma unroll
    for (int i = 0; i < 8; i++)
        #pragma unroll
        for (int j = 0; j < 8; j++) acc[i][j] = 0.0f;

    // prefetch k0 = 0
    float4 av = make_float4(0.f, 0.f, 0.f, 0.f);
    if (a_guard) av = *(const float4*)(a_ptr);
    float4 bv = *(const float4*)(b_ptr);

    for (int k0 = 0; k0 < DD; k0 += 8) {
        As[a_col + 0][a_row] = av.x;
        As[a_col + 1][a_row] = av.y;
        As[a_col + 2][a_row] = av.z;
        As[a_col + 3][a_row] = av.w;
        *(float4*)&Bs[b_row][b_col] = bv;
        __syncthreads();

        // issue next tile's loads; they retire under the FMA loop
        if (k0 + 8 < DD) {
            if (a_guard) av = *(const float4*)(a_ptr + k0 + 8);
            bv = *(const float4*)(b_ptr + (size_t)(k0 + 8) * DD);
        }

        #pragma unroll
        for (int kk = 0; kk < 8; kk++) {
            float ra[8], rb[8];
            *(float4*)&ra[0] = *(const float4*)&As[kk][ty * 8 + 0];
            *(float4*)&ra[4] = *(const float4*)&As[kk][ty * 8 + 4];
            *(float4*)&rb[0] = *(const float4*)&Bs[kk][tx * 8 + 0];
            *(float4*)&rb[4] = *(const float4*)&Bs[kk][tx * 8 + 4];
            #pragma unroll
            for (int i = 0; i < 8; i++)
                #pragma unroll
                for (int j = 0; j < 8; j++)
                    acc[i][j] = fmaf(ra[i], rb[j], acc[i][j]);
        }
        __syncthreads();
    }

    #pragma unroll
    for (int i = 0; i < 8; i++) {
        const int gr = block_row + ty * 8 + i;
        if (gr < ROWS) {
            __half2 h[4];
            #pragma unroll
            for (int j = 0; j < 4; j++)
                h[j] = __float22half2_rn(make_float2(acc[i][2 * j], acc[i][2 * j + 1]));
            *(uint4*)(C + (size_t)gr * DD + block_col + tx * 8) = *(uint4*)h;
        }
    }
}

// ---------------- K2: fused edge scores + exp + segment scatter -------------
// One warp per (b, edge). q/k rows are fp16 (512 B each); lane covers 8 values,
// 4 lanes per head. e = exp(dot/16) written to out; seg accumulated via
// vectorized red.global.add.v4.f32 (2 per edge instead of 8 scalar atomics).
__device__ __forceinline__ float hdot8(uint4 q, uint4 k) {
    const __half2* qh = (const __half2*)&q;
    const __half2* kh = (const __half2*)&k;
    float s = 0.0f;
    #pragma unroll
    for (int j = 0; j < 4; j++) {
        float2 qf = __half22float2(qh[j]);
        float2 kf = __half22float2(kh[j]);
        s = fmaf(qf.x, kf.x, s);
        s = fmaf(qf.y, kf.y, s);
    }
    return s;
}

__global__ void __launch_bounds__(256)
edge_fused_kernel(float* __restrict__ out) {
    const int warp = (blockIdx.x * blockDim.x + threadIdx.x) >> 5;
    const int lane = threadIdx.x & 31;
    if (warp >= TOTAL_E) return;   // grid is exact: no partial warps

    const int b = warp / MM;
    const int m = warp - b * MM;
    const int i0 = g_mask32[m];
    const int i1 = g_mask32[MM + m];

    const uint4* q4 = (const uint4*)(g_qh + ((size_t)b * NN + i0) * DD);
    const uint4* k4 = (const uint4*)(g_kh + ((size_t)b * NN + i1) * DD);

    float p = hdot8(q4[lane], k4[lane]);

    // reduce within 4-lane head groups
    p += __shfl_down_sync(0xffffffffu, p, 2, 4);
    p += __shfl_down_sync(0xffffffffu, p, 1, 4);

    float e = 0.0f;
    if ((lane & 3) == 0) {
        e = __expf(p * 0.0625f);                       // / sqrt(256); no max-sub
        out[(size_t)warp * HH + (lane >> 2)] = e;      // head = lane/4
    }

    // gather 4 head values into lanes 0 (heads 0-3) and 16 (heads 4-7)
    float4 vv;
    vv.x = __shfl_sync(0xffffffffu, e, (lane & 16) + 0);
    vv.y = __shfl_sync(0xffffffffu, e, (lane & 16) + 4);
    vv.z = __shfl_sync(0xffffffffu, e, (lane & 16) + 8);
    vv.w = __shfl_sync(0xffffffffu, e, (lane & 16) + 12);

    if ((lane & 15) == 0) {
        float* segp = g_seg + ((size_t)b * NN + i0) * HH + (lane >> 2);
        asm volatile("red.global.add.v4.f32 [%0], {%1, %2, %3, %4};"
                     :: "l"(segp), "f"(vv.x), "f"(vv.y), "f"(vv.z), "f"(vv.w)
                     : "memory");
    }
}

// ---------------- K3: out = e / (seg[idx] + 1e-16) in place ------------------
__global__ void __launch_bounds__(256)
normalize_kernel(float* __restrict__ e) {
    const int t = blockIdx.x * blockDim.x + threadIdx.x;
    if (t >= TOTAL_E) return;
    const int b = t / MM;
    const int m = t - b * MM;
    const int i0 = g_mask32[m];

    const float4* segp = (const float4*)(g_seg + ((size_t)b * NN + i0) * HH);
    float4 s0 = segp[0], s1 = segp[1];

    const size_t base = (size_t)t * HH;
    float4 e0 = *(float4*)(e + base);
    float4 e1 = *(float4*)(e + base + 4);

    e0.x /= (s0.x + 1e-16f);
    e0.y /= (s0.y + 1e-16f);
    e0.z /= (s0.z + 1e-16f);
    e0.w /= (s0.w + 1e-16f);
    e1.x /= (s1.x + 1e-16f);
    e1.y /= (s1.y + 1e-16f);
    e1.z /= (s1.z + 1e-16f);
    e1.w /= (s1.w + 1e-16f);

    *(float4*)(e + base)     = e0;
    *(float4*)(e + base + 4) = e1;
}

// ---------------- launch ----------------------------------------------------
extern "C" void kernel_launch(void* const* d_in, const int* in_sizes, int n_in,
                              void* d_out, int out_size) {
    const float* x_q  = (const float*)d_in[0];
    const float* x_k  = (const float*)d_in[1];
    const void*  mask = (const void*)d_in[2];
    const float* w_q  = (const float*)d_in[3];
    const float* w_k  = (const float*)d_in[4];
    float* out = (float*)d_out;

    // K_pre: detect mask dtype, normalize to int32, zero seg
    detect_mask_kernel<<<1, 256>>>((const unsigned*)mask);
    convert_mask_kernel<<<(2 * MM + 255) / 256, 256>>>(mask);

    // K1: q = x_q@w_q, k = x_k@w_k (fp32 compute, fp16 store)
    {
        dim3 grid((ROWS + 127) / 128, DD / 128, 2);
        gemm_kernel<<<grid, 256>>>(x_q, x_k, w_q, w_k);
    }
    // K2: fused edge scores + exp + segment scatter
    {
        int warps_per_block = 256 / 32;
        int blocks = (TOTAL_E + warps_per_block - 1) / warps_per_block;
        edge_fused_kernel<<<blocks, 256>>>(out);
    }
    // K3: normalize
    {
        int blocks = (TOTAL_E + 255) / 256;
        normalize_kernel<<<blocks, 256>>>(out);
    }
}

// round 4
// speedup vs baseline: 1.7834x; 1.3112x over previous
#include <cuda_runtime.h>
#include <cuda_fp16.h>
#include <mma.h>
#include <cstdint>

using namespace nvcuda;

// Problem constants
#define BB 2
#define NN 10000
#define MM 320000
#define DD 256
#define HH 8
#define ROWS (BB * NN)          // 20000 flattened GEMM rows
#define MPAD 20096              // 157 * 128: padded so GEMM needs no guards
#define TOTAL_E (BB * MM)       // 640000 (b, edge) pairs
#define BK 32

// ---------------- scratch (device globals; no allocation allowed) ----------
__device__ __half g_xh[2 * (size_t)MPAD * DD];  // fp16 x_q | x_k (padded rows zeroed)
__device__ __half g_wh[2 * DD * DD];            // fp16 w_q | w_k
__device__ __half g_qh[(size_t)MPAD * DD];      // fp16 q
__device__ __half g_kh[(size_t)MPAD * DD];      // fp16 k
__device__ float  g_seg[(size_t)BB * NN * HH];  // 640 KB
__device__ int    g_mask32[2 * MM];             // canonical int32 mask
__device__ int    g_is64;                       // detected mask dtype

// ---------------- K_pre0: detect mask dtype ---------------------------------
// int64 indices in [0,N): every odd 32-bit word is 0. int32: odd words random.
__global__ void detect_mask_kernel(const unsigned* __restrict__ mraw) {
    __shared__ int any_nonzero;
    if (threadIdx.x == 0) any_nonzero = 0;
    __syncthreads();
    unsigned v = mraw[threadIdx.x * 2 + 1];
    if (v != 0u) atomicOr(&any_nonzero, 1);
    __syncthreads();
    if (threadIdx.x == 0) g_is64 = any_nonzero ? 0 : 1;
}

// ---------------- K_pre1: normalize mask to int32 (clamped) + reset seg -----
__global__ void convert_mask_kernel(const void* __restrict__ mraw) {
    int t = blockIdx.x * blockDim.x + threadIdx.x;
    if (t < 2 * MM) {
        long long v;
        if (g_is64) v = ((const long long*)mraw)[t];
        else        v = (long long)((const int*)mraw)[t];
        int vi = (int)v;
        vi = vi < 0 ? 0 : (vi >= NN ? NN - 1 : vi);
        g_mask32[t] = vi;
    }
    if (t < BB * NN * HH) g_seg[t] = 0.0f;
}

// ---------------- K_pre2: fp32 -> fp16 conversion of x and w ----------------
// 8 elements per thread. x region first (2 matrices, MPAD rows each,
// zero-filling pad rows), then the two 256x256 weights.
__global__ void convert_inputs_kernel(const float* __restrict__ xq,
                                      const float* __restrict__ xk,
                                      const float* __restrict__ wq,
                                      const float* __restrict__ wk) {
    const int t = blockIdx.x * blockDim.x + threadIdx.x;
    const int XT = 2 * MPAD * (DD / 8);   // threads covering x region
    if (t < XT) {
        const int per_mat = MPAD * (DD / 8);
        const int mat = t / per_mat;
        const int r   = (t % per_mat) / (DD / 8);
        const int c   = (t % (DD / 8)) * 8;
        __half2 h[4];
        if (r < ROWS) {
            const float* src = (mat == 0 ? xq : xk) + (size_t)r * DD + c;
            float4 f0 = *(const float4*)(src);
            float4 f1 = *(const float4*)(src + 4);
            h[0] = __float22half2_rn(make_float2(f0.x, f0.y));
            h[1] = __float22half2_rn(make_float2(f0.z, f0.w));
            h[2] = __float22half2_rn(make_float2(f1.x, f1.y));
            h[3] = __float22half2_rn(make_float2(f1.z, f1.w));
        } else {
            h[0] = h[1] = h[2] = h[3] = __float2half2_rn(0.0f);
        }
        *(uint4*)(g_xh + (size_t)mat * MPAD * DD + (size_t)r * DD + c) = *(uint4*)h;
    } else {
        const int u = t - XT;
        const int WT = 2 * (DD * DD / 8);
        if (u < WT) {
            const int per_mat = DD * DD / 8;
            const int mat = u / per_mat;
            const int e   = (u % per_mat) * 8;
            const float* src = (mat == 0 ? wq : wk) + e;
            float4 f0 = *(const float4*)(src);
            float4 f1 = *(const float4*)(src + 4);
            __half2 h[4];
            h[0] = __float22half2_rn(make_float2(f0.x, f0.y));
            h[1] = __float22half2_rn(make_float2(f0.z, f0.w));
            h[2] = __float22half2_rn(make_float2(f1.x, f1.y));
            h[3] = __float22half2_rn(make_float2(f1.z, f1.w));
            *(uint4*)(g_wh + (size_t)mat * DD * DD + e) = *(uint4*)h;
        }
    }
}

// ---------------- K1: HMMA GEMM  C = A(fp16) * W(fp16), fp32 acc, fp16 out --
// BM=128, BN=128, BK=32. 8 warps in 4x2, each owns 32x64 (2x4 wmma frags).
// smem-staged tiles, register prefetch of next k-step. No bounds checks
// (M padded to MPAD).
__global__ void __launch_bounds__(256)
gemm_wmma_kernel() {
    const int mat = blockIdx.z;
    const __half* A = g_xh + (size_t)mat * MPAD * DD;
    const __half* B = g_wh + (size_t)mat * DD * DD;
    __half*       C = (mat == 0) ? g_qh : g_kh;

    __shared__ __half As[128 * BK];    // row-major, ld=BK
    __shared__ __half Bs[BK * 128];    // row-major, ld=128
    __shared__ float  stage[8][256];   // per-warp 16x16 f32 staging

    const int tid  = threadIdx.x;
    const int warp = tid >> 5;
    const int lane = tid & 31;
    const int wm = warp >> 1;          // 0..3
    const int wn = warp & 1;           // 0..1
    const int block_row = blockIdx.x * 128;
    const int block_col = blockIdx.y * 128;

    // A load: thread t -> row t/2, halves (t&1)*16 + {0..7, 8..15}
    const int a_r = tid >> 1;
    const int a_c = (tid & 1) * 16;
    const __half* a_src = A + (size_t)(block_row + a_r) * DD + a_c;
    // B load: idx in {tid, tid+256}: row idx/16, col (idx%16)*8
    const int b_r0 = tid >> 4,          b_c0 = (tid & 15) * 8;
    const int b_r1 = (tid + 256) >> 4,  b_c1 = ((tid + 256) & 15) * 8;
    const __half* b_src0 = B + (size_t)b_r0 * DD + block_col + b_c0;
    const __half* b_src1 = B + (size_t)b_r1 * DD + block_col + b_c1;

    wmma::fragment<wmma::accumulator, 16, 16, 16, float> acc[2][4];
    #pragma unroll
    for (int i = 0; i < 2; i++)
        #pragma unroll
        for (int j = 0; j < 4; j++) wmma::fill_fragment(acc[i][j], 0.0f);

    // prefetch k0 = 0
    uint4 av0 = *(const uint4*)(a_src);
    uint4 av1 = *(const uint4*)(a_src + 8);
    uint4 bv0 = *(const uint4*)(b_src0);
    uint4 bv1 = *(const uint4*)(b_src1);

    for (int k0 = 0; k0 < DD; k0 += BK) {
        *(uint4*)(As + a_r * BK + a_c)     = av0;
        *(uint4*)(As + a_r * BK + a_c + 8) = av1;
        *(uint4*)(Bs + b_r0 * 128 + b_c0)  = bv0;
        *(uint4*)(Bs + b_r1 * 128 + b_c1)  = bv1;
        __syncthreads();

        if (k0 + BK < DD) {            // issue next tile's loads early
            av0 = *(const uint4*)(a_src + k0 + BK);
            av1 = *(const uint4*)(a_src + k0 + BK + 8);
            bv0 = *(const uint4*)(b_src0 + (size_t)(k0 + BK) * DD);
            bv1 = *(const uint4*)(b_src1 + (size_t)(k0 + BK) * DD);
        }

        #pragma unroll
        for (int kk = 0; kk < BK; kk += 16) {
            wmma::fragment<wmma::matrix_a, 16, 16, 16, __half, wmma::row_major> af[2];
            wmma::fragment<wmma::matrix_b, 16, 16, 16, __half, wmma::row_major> bf[4];
            #pragma unroll
            for (int i = 0; i < 2; i++)
                wmma::load_matrix_sync(af[i], As + (wm * 32 + 16 * i) * BK + kk, BK);
            #pragma unroll
            for (int j = 0; j < 4; j++)
                wmma::load_matrix_sync(bf[j], Bs + kk * 128 + wn * 64 + 16 * j, 128);
            #pragma unroll
            for (int i = 0; i < 2; i++)
                #pragma unroll
                for (int j = 0; j < 4; j++)
                    wmma::mma_sync(acc[i][j], af[i], bf[j], acc[i][j]);
        }
        __syncthreads();
    }

    // epilogue: f32 acc -> smem -> fp16 gmem (warp-private staging)
    #pragma unroll
    for (int i = 0; i < 2; i++) {
        #pragma unroll
        for (int j = 0; j < 4; j++) {
            wmma::store_matrix_sync(&stage[warp][0], acc[i][j], 16, wmma::mem_row_major);
            __syncwarp();
            const int r = lane >> 1, c = (lane & 1) * 8;
            const float* sp = &stage[warp][r * 16 + c];
            __half2 h[4];
            #pragma unroll
            for (int x = 0; x < 4; x++)
                h[x] = __float22half2_rn(make_float2(sp[2 * x], sp[2 * x + 1]));
            __half* cp = C + (size_t)(block_row + wm * 32 + 16 * i + r) * DD
                       + block_col + wn * 64 + 16 * j + c;
            *(uint4*)cp = *(uint4*)h;
            __syncwarp();
        }
    }
}

// ---------------- K2: fused edge scores + exp + segment scatter -------------
// One warp per (b, edge). fp16 q/k rows (512 B); 4 lanes per head.
__device__ __forceinline__ float hdot8(uint4 q, uint4 k) {
    const __half2* qh = (const __half2*)&q;
    const __half2* kh = (const __half2*)&k;
    float s = 0.0f;
    #pragma unroll
    for (int j = 0; j < 4; j++) {
        float2 qf = __half22float2(qh[j]);
        float2 kf = __half22float2(kh[j]);
        s = fmaf(qf.x, kf.x, s);
        s = fmaf(qf.y, kf.y, s);
    }
    return s;
}

__global__ void __launch_bounds__(256)
edge_fused_kernel(float* __restrict__ out) {
    const int warp = (blockIdx.x * blockDim.x + threadIdx.x) >> 5;
    const int lane = threadIdx.x & 31;
    if (warp >= TOTAL_E) return;

    const int b = warp / MM;
    const int m = warp - b * MM;
    const int i0 = g_mask32[m];
    const int i1 = g_mask32[MM + m];

    const uint4* q4 = (const uint4*)(g_qh + ((size_t)b * NN + i0) * DD);
    const uint4* k4 = (const uint4*)(g_kh + ((size_t)b * NN + i1) * DD);

    float p = hdot8(q4[lane], k4[lane]);

    // reduce within 4-lane head groups
    p += __shfl_down_sync(0xffffffffu, p, 2, 4);
    p += __shfl_down_sync(0xffffffffu, p, 1, 4);

    float e = 0.0f;
    if ((lane & 3) == 0) {
        e = __expf(p * 0.0625f);                       // / sqrt(256); no max-sub
        out[(size_t)warp * HH + (lane >> 2)] = e;      // head = lane/4
    }

    // gather 4 head values into lanes 0 (heads 0-3) and 16 (heads 4-7)
    float4 vv;
    vv.x = __shfl_sync(0xffffffffu, e, (lane & 16) + 0);
    vv.y = __shfl_sync(0xffffffffu, e, (lane & 16) + 4);
    vv.z = __shfl_sync(0xffffffffu, e, (lane & 16) + 8);
    vv.w = __shfl_sync(0xffffffffu, e, (lane & 16) + 12);

    if ((lane & 15) == 0) {
        float* segp = g_seg + ((size_t)b * NN + i0) * HH + (lane >> 2);
        asm volatile("red.global.add.v4.f32 [%0], {%1, %2, %3, %4};"
                     :: "l"(segp), "f"(vv.x), "f"(vv.y), "f"(vv.z), "f"(vv.w)
                     : "memory");
    }
}

// ---------------- K3: out = e / (seg[idx] + 1e-16) in place ------------------
__global__ void __launch_bounds__(256)
normalize_kernel(float* __restrict__ e) {
    const int t = blockIdx.x * blockDim.x + threadIdx.x;
    if (t >= TOTAL_E) return;
    const int b = t / MM;
    const int m = t - b * MM;
    const int i0 = g_mask32[m];

    const float4* segp = (const float4*)(g_seg + ((size_t)b * NN + i0) * HH);
    float4 s0 = segp[0], s1 = segp[1];

    const size_t base = (size_t)t * HH;
    float4 e0 = *(float4*)(e + base);
    float4 e1 = *(float4*)(e + base + 4);

    e0.x /= (s0.x + 1e-16f);
    e0.y /= (s0.y + 1e-16f);
    e0.z /= (s0.z + 1e-16f);
    e0.w /= (s0.w + 1e-16f);
    e1.x /= (s1.x + 1e-16f);
    e1.y /= (s1.y + 1e-16f);
    e1.z /= (s1.z + 1e-16f);
    e1.w /= (s1.w + 1e-16f);

    *(float4*)(e + base)     = e0;
    *(float4*)(e + base + 4) = e1;
}

// ---------------- launch ----------------------------------------------------
extern "C" void kernel_launch(void* const* d_in, const int* in_sizes, int n_in,
                              void* d_out, int out_size) {
    const float* x_q  = (const float*)d_in[0];
    const float* x_k  = (const float*)d_in[1];
    const void*  mask = (const void*)d_in[2];
    const float* w_q  = (const float*)d_in[3];
    const float* w_k  = (const float*)d_in[4];
    float* out = (float*)d_out;

    // K_pre: detect mask dtype, normalize to int32, zero seg, fp16 convert
    detect_mask_kernel<<<1, 256>>>((const unsigned*)mask);
    convert_mask_kernel<<<(2 * MM + 255) / 256, 256>>>(mask);
    {
        int total = 2 * MPAD * (DD / 8) + 2 * (DD * DD / 8);
        convert_inputs_kernel<<<(total + 255) / 256, 256>>>(x_q, x_k, w_q, w_k);
    }
    // K1: q = x_q@w_q, k = x_k@w_k on tensor cores
    {
        dim3 grid(MPAD / 128, DD / 128, 2);
        gemm_wmma_kernel<<<grid, 256>>>();
    }
    // K2: fused edge scores + exp + segment scatter
    {
        int warps_per_block = 256 / 32;
        int blocks = (TOTAL_E + warps_per_block - 1) / warps_per_block;
        edge_fused_kernel<<<blocks, 256>>>(out);
    }
    // K3: normalize
    {
        int blocks = (TOTAL_E + 255) / 256;
        normalize_kernel<<<blocks, 256>>>(out);
    }
}

// round 5
// speedup vs baseline: 2.3386x; 1.3113x over previous
#include <cuda_runtime.h>
#include <cuda_fp16.h>
#include <mma.h>
#include <cstdint>

using namespace nvcuda;

// Problem constants
#define BB 2
#define NN 10000
#define MM 320000
#define DD 256
#define HH 8
#define ROWS (BB * NN)          // 20000 flattened GEMM rows
#define MPAD 20096              // 157 * 128: padded so GEMM needs no guards
#define TOTAL_E (BB * MM)       // 640000 (b, edge) pairs
#define BK 32
#define LDA 40                  // As padded stride (halves): 80B, conflict-free LDSM
#define LDB 136                 // Bs padded stride (halves): 272B, conflict-free LDSM
#define LDS_STAGE 20            // epilogue staging stride (floats)

// ---------------- scratch (device globals; no allocation allowed) ----------
__device__ __half g_xh[2 * (size_t)MPAD * DD];  // fp16 x_q | x_k (padded rows zeroed)
__device__ __half g_wh[2 * DD * DD];            // fp16 w_q | w_k
__device__ __half g_qh[(size_t)MPAD * DD];      // fp16 q
__device__ __half g_kh[(size_t)MPAD * DD];      // fp16 k
__device__ float  g_seg[(size_t)BB * NN * HH];  // 640 KB
__device__ int    g_mask32[2 * MM];             // canonical int32 mask
__device__ int    g_is64;                       // detected mask dtype

// ---------------- K_pre0: detect mask dtype ---------------------------------
// int64 indices in [0,N): every odd 32-bit word is 0. int32: odd words random.
__global__ void detect_mask_kernel(const unsigned* __restrict__ mraw) {
    __shared__ int any_nonzero;
    if (threadIdx.x == 0) any_nonzero = 0;
    __syncthreads();
    unsigned v = mraw[threadIdx.x * 2 + 1];
    if (v != 0u) atomicOr(&any_nonzero, 1);
    __syncthreads();
    if (threadIdx.x == 0) g_is64 = any_nonzero ? 0 : 1;
}

// ---------------- K_pre1: normalize mask to int32 (clamped) + reset seg -----
__global__ void convert_mask_kernel(const void* __restrict__ mraw) {
    int t = blockIdx.x * blockDim.x + threadIdx.x;
    if (t < 2 * MM) {
        long long v;
        if (g_is64) v = ((const long long*)mraw)[t];
        else        v = (long long)((const int*)mraw)[t];
        int vi = (int)v;
        vi = vi < 0 ? 0 : (vi >= NN ? NN - 1 : vi);
        g_mask32[t] = vi;
    }
    if (t < BB * NN * HH) g_seg[t] = 0.0f;
}

// ---------------- K_pre2: fp32 -> fp16 conversion of x and w ----------------
__global__ void convert_inputs_kernel(const float* __restrict__ xq,
                                      const float* __restrict__ xk,
                                      const float* __restrict__ wq,
                                      const float* __restrict__ wk) {
    const int t = blockIdx.x * blockDim.x + threadIdx.x;
    const int XT = 2 * MPAD * (DD / 8);   // threads covering x region
    if (t < XT) {
        const int per_mat = MPAD * (DD / 8);
        const int mat = t / per_mat;
        const int r   = (t % per_mat) / (DD / 8);
        const int c   = (t % (DD / 8)) * 8;
        __half2 h[4];
        if (r < ROWS) {
            const float* src = (mat == 0 ? xq : xk) + (size_t)r * DD + c;
            float4 f0 = *(const float4*)(src);
            float4 f1 = *(const float4*)(src + 4);
            h[0] = __float22half2_rn(make_float2(f0.x, f0.y));
            h[1] = __float22half2_rn(make_float2(f0.z, f0.w));
            h[2] = __float22half2_rn(make_float2(f1.x, f1.y));
            h[3] = __float22half2_rn(make_float2(f1.z, f1.w));
        } else {
            h[0] = h[1] = h[2] = h[3] = __float2half2_rn(0.0f);
        }
        *(uint4*)(g_xh + (size_t)mat * MPAD * DD + (size_t)r * DD + c) = *(uint4*)h;
    } else {
        const int u = t - XT;
        const int WT = 2 * (DD * DD / 8);
        if (u < WT) {
            const int per_mat = DD * DD / 8;
            const int mat = u / per_mat;
            const int e   = (u % per_mat) * 8;
            const float* src = (mat == 0 ? wq : wk) + e;
            float4 f0 = *(const float4*)(src);
            float4 f1 = *(const float4*)(src + 4);
            __half2 h[4];
            h[0] = __float22half2_rn(make_float2(f0.x, f0.y));
            h[1] = __float22half2_rn(make_float2(f0.z, f0.w));
            h[2] = __float22half2_rn(make_float2(f1.x, f1.y));
            h[3] = __float22half2_rn(make_float2(f1.z, f1.w));
            *(uint4*)(g_wh + (size_t)mat * DD * DD + e) = *(uint4*)h;
        }
    }
}

// ---------------- K1: HMMA GEMM  C = A(fp16) * W(fp16), fp32 acc, fp16 out --
// BM=128, BN=128, BK=32. 8 warps in 4x2, each owns 32x64 (2x4 wmma frags).
// Padded smem strides (LDA=40, LDB=136) so LDSM fragment loads are
// bank-conflict-free. Register prefetch of next k-tile. No bounds checks.
__global__ void __launch_bounds__(256)
gemm_wmma_kernel() {
    const int mat = blockIdx.z;
    const __half* A = g_xh + (size_t)mat * MPAD * DD;
    const __half* B = g_wh + (size_t)mat * DD * DD;
    __half*       C = (mat == 0) ? g_qh : g_kh;

    __shared__ __half As[128 * LDA];          // padded: 10 KB
    __shared__ __half Bs[BK * LDB];           // padded: 8.5 KB
    __shared__ float  stage[8][16 * LDS_STAGE]; // per-warp staging, 10 KB

    const int tid  = threadIdx.x;
    const int warp = tid >> 5;
    const int lane = tid & 31;
    const int wm = warp >> 1;          // 0..3
    const int wn = warp & 1;           // 0..1
    const int block_row = blockIdx.x * 128;
    const int block_col = blockIdx.y * 128;

    // A load: thread t -> row t/2, halves (t&1)*16 + {0..7, 8..15}
    const int a_r = tid >> 1;
    const int a_c = (tid & 1) * 16;
    const __half* a_src = A + (size_t)(block_row + a_r) * DD + a_c;
    // B load: idx in {tid, tid+256}: row idx/16, col (idx%16)*8
    const int b_r0 = tid >> 4,          b_c0 = (tid & 15) * 8;
    const int b_r1 = (tid + 256) >> 4,  b_c1 = ((tid + 256) & 15) * 8;
    const __half* b_src0 = B + (size_t)b_r0 * DD + block_col + b_c0;
    const __half* b_src1 = B + (size_t)b_r1 * DD + block_col + b_c1;

    wmma::fragment<wmma::accumulator, 16, 16, 16, float> acc[2][4];
    #pragma unroll
    for (int i = 0; i < 2; i++)
        #pragma unroll
        for (int j = 0; j < 4; j++) wmma::fill_fragment(acc[i][j], 0.0f);

    // prefetch k0 = 0
    uint4 av0 = *(const uint4*)(a_src);
    uint4 av1 = *(const uint4*)(a_src + 8);
    uint4 bv0 = *(const uint4*)(b_src0);
    uint4 bv1 = *(const uint4*)(b_src1);

    for (int k0 = 0; k0 < DD; k0 += BK) {
        *(uint4*)(As + a_r * LDA + a_c)     = av0;
        *(uint4*)(As + a_r * LDA + a_c + 8) = av1;
        *(uint4*)(Bs + b_r0 * LDB + b_c0)   = bv0;
        *(uint4*)(Bs + b_r1 * LDB + b_c1)   = bv1;
        __syncthreads();

        if (k0 + BK < DD) {            // issue next tile's loads early
            av0 = *(const uint4*)(a_src + k0 + BK);
            av1 = *(const uint4*)(a_src + k0 + BK + 8);
            bv0 = *(const uint4*)(b_src0 + (size_t)(k0 + BK) * DD);
            bv1 = *(const uint4*)(b_src1 + (size_t)(k0 + BK) * DD);
        }

        #pragma unroll
        for (int kk = 0; kk < BK; kk += 16) {
            wmma::fragment<wmma::matrix_a, 16, 16, 16, __half, wmma::row_major> af[2];
            wmma::fragment<wmma::matrix_b, 16, 16, 16, __half, wmma::row_major> bf[4];
            #pragma unroll
            for (int i = 0; i < 2; i++)
                wmma::load_matrix_sync(af[i], As + (wm * 32 + 16 * i) * LDA + kk, LDA);
            #pragma unroll
            for (int j = 0; j < 4; j++)
                wmma::load_matrix_sync(bf[j], Bs + kk * LDB + wn * 64 + 16 * j, LDB);
            #pragma unroll
            for (int i = 0; i < 2; i++)
                #pragma unroll
                for (int j = 0; j < 4; j++)
                    wmma::mma_sync(acc[i][j], af[i], bf[j], acc[i][j]);
        }
        __syncthreads();
    }

    // epilogue: f32 acc -> smem (padded) -> fp16 gmem
    #pragma unroll
    for (int i = 0; i < 2; i++) {
        #pragma unroll
        for (int j = 0; j < 4; j++) {
            wmma::store_matrix_sync(&stage[warp][0], acc[i][j], LDS_STAGE,
                                    wmma::mem_row_major);
            __syncwarp();
            const int r = lane >> 1, c = (lane & 1) * 8;
            const float* sp = &stage[warp][r * LDS_STAGE + c];
            __half2 h[4];
            #pragma unroll
            for (int x = 0; x < 4; x++)
                h[x] = __float22half2_rn(make_float2(sp[2 * x], sp[2 * x + 1]));
            __half* cp = C + (size_t)(block_row + wm * 32 + 16 * i + r) * DD
                       + block_col + wn * 64 + 16 * j + c;
            *(uint4*)cp = *(uint4*)h;
            __syncwarp();
        }
    }
}

// ---------------- K2: fused edge scores + exp + segment scatter -------------
// One warp per (b, edge). fp16 q/k rows (512 B); 4 lanes per head.
__device__ __forceinline__ float hdot8(uint4 q, uint4 k) {
    const __half2* qh = (const __half2*)&q;
    const __half2* kh = (const __half2*)&k;
    float s = 0.0f;
    #pragma unroll
    for (int j = 0; j < 4; j++) {
        float2 qf = __half22float2(qh[j]);
        float2 kf = __half22float2(kh[j]);
        s = fmaf(qf.x, kf.x, s);
        s = fmaf(qf.y, kf.y, s);
    }
    return s;
}

__global__ void __launch_bounds__(256)
edge_fused_kernel(float* __restrict__ out) {
    const int warp = (blockIdx.x * blockDim.x + threadIdx.x) >> 5;
    const int lane = threadIdx.x & 31;
    if (warp >= TOTAL_E) return;

    const int b = warp / MM;
    const int m = warp - b * MM;
    const int i0 = g_mask32[m];
    const int i1 = g_mask32[MM + m];

    const uint4* q4 = (const uint4*)(g_qh + ((size_t)b * NN + i0) * DD);
    const uint4* k4 = (const uint4*)(g_kh + ((size_t)b * NN + i1) * DD);

    float p = hdot8(q4[lane], k4[lane]);

    // reduce within 4-lane head groups
    p += __shfl_down_sync(0xffffffffu, p, 2, 4);
    p += __shfl_down_sync(0xffffffffu, p, 1, 4);

    float e = 0.0f;
    if ((lane & 3) == 0) {
        e = __expf(p * 0.0625f);                       // / sqrt(256); no max-sub
        out[(size_t)warp * HH + (lane >> 2)] = e;      // head = lane/4
    }

    // gather 4 head values into lanes 0 (heads 0-3) and 16 (heads 4-7)
    float4 vv;
    vv.x = __shfl_sync(0xffffffffu, e, (lane & 16) + 0);
    vv.y = __shfl_sync(0xffffffffu, e, (lane & 16) + 4);
    vv.z = __shfl_sync(0xffffffffu, e, (lane & 16) + 8);
    vv.w = __shfl_sync(0xffffffffu, e, (lane & 16) + 12);

    if ((lane & 15) == 0) {
        float* segp = g_seg + ((size_t)b * NN + i0) * HH + (lane >> 2);
        asm volatile("red.global.add.v4.f32 [%0], {%1, %2, %3, %4};"
                     :: "l"(segp), "f"(vv.x), "f"(vv.y), "f"(vv.z), "f"(vv.w)
                     : "memory");
    }
}

// ---------------- K3: out = e / (seg[idx] + 1e-16) in place ------------------
__global__ void __launch_bounds__(256)
normalize_kernel(float* __restrict__ e) {
    const int t = blockIdx.x * blockDim.x + threadIdx.x;
    if (t >= TOTAL_E) return;
    const int b = t / MM;
    const int m = t - b * MM;
    const int i0 = g_mask32[m];

    const float4* segp = (const float4*)(g_seg + ((size_t)b * NN + i0) * HH);
    float4 s0 = segp[0], s1 = segp[1];

    const size_t base = (size_t)t * HH;
    float4 e0 = *(float4*)(e + base);
    float4 e1 = *(float4*)(e + base + 4);

    e0.x /= (s0.x + 1e-16f);
    e0.y /= (s0.y + 1e-16f);
    e0.z /= (s0.z + 1e-16f);
    e0.w /= (s0.w + 1e-16f);
    e1.x /= (s1.x + 1e-16f);
    e1.y /= (s1.y + 1e-16f);
    e1.z /= (s1.z + 1e-16f);
    e1.w /= (s1.w + 1e-16f);

    *(float4*)(e + base)     = e0;
    *(float4*)(e + base + 4) = e1;
}

// ---------------- launch ----------------------------------------------------
extern "C" void kernel_launch(void* const* d_in, const int* in_sizes, int n_in,
                              void* d_out, int out_size) {
    const float* x_q  = (const float*)d_in[0];
    const float* x_k  = (const float*)d_in[1];
    const void*  mask = (const void*)d_in[2];
    const float* w_q  = (const float*)d_in[3];
    const float* w_k  = (const float*)d_in[4];
    float* out = (float*)d_out;

    // K_pre: detect mask dtype, normalize to int32, zero seg, fp16 convert
    detect_mask_kernel<<<1, 256>>>((const unsigned*)mask);
    convert_mask_kernel<<<(2 * MM + 255) / 256, 256>>>(mask);
    {
        int total = 2 * MPAD * (DD / 8) + 2 * (DD * DD / 8);
        convert_inputs_kernel<<<(total + 255) / 256, 256>>>(x_q, x_k, w_q, w_k);
    }
    // K1: q = x_q@w_q, k = x_k@w_k on tensor cores
    {
        dim3 grid(MPAD / 128, DD / 128, 2);
        gemm_wmma_kernel<<<grid, 256>>>();
    }
    // K2: fused edge scores + exp + segment scatter
    {
        int warps_per_block = 256 / 32;
        int blocks = (TOTAL_E + warps_per_block - 1) / warps_per_block;
        edge_fused_kernel<<<blocks, 256>>>(out);
    }
    // K3: normalize
    {
        int blocks = (TOTAL_E + 255) / 256;
        normalize_kernel<<<blocks, 256>>>(out);
    }
}